// round 8
// baseline (speedup 1.0000x reference)
#include <cuda_runtime.h>
#include <cstdint>
#include <math.h>

#define DIMC  512
#define NH    8
#define HD    64
#define NB    8
#define NSEQ  1024
#define QK_SCALE 0.125f

// Scratch (device globals)
__device__ float g_q[NB * NH * NSEQ * HD];      // permuted, rounded, scaled
__device__ float g_k[NB * NH * NSEQ * HD];      // permuted, rounded
__device__ float g_v[NB * NH * NSEQ * HD];      // natural, rounded
__device__ float g_attnp[NB * NSEQ * DIMC];     // permuted, rounded
__device__ float g_xp[NB * NSEQ * DIMC];        // permuted, rounded x
__device__ float g_wqkvp[3 * DIMC * DIMC];      // permuted, rounded qkv_w
__device__ float g_wprojp[DIMC * DIMC];         // permuted, rounded proj_w

__device__ __forceinline__ uint32_t f2tf(float f) {
    uint32_t r;
    asm("cvt.rna.tf32.f32 %0, %1;" : "=r"(r) : "f"(f));
    return r;
}
__device__ __forceinline__ float rndf(float f) { return __uint_as_float(f2tf(f)); }
__device__ __forceinline__ void mma8(float* d, const uint32_t* a, uint32_t b0, uint32_t b1) {
    asm volatile(
        "mma.sync.aligned.m16n8k8.row.col.f32.tf32.tf32.f32 "
        "{%0,%1,%2,%3}, {%4,%5,%6,%7}, {%8,%9}, {%0,%1,%2,%3};"
        : "+f"(d[0]), "+f"(d[1]), "+f"(d[2]), "+f"(d[3])
        : "r"(a[0]), "r"(a[1]), "r"(a[2]), "r"(a[3]), "r"(b0), "r"(b1));
}
__device__ __forceinline__ uint32_t smem_u32(const void* p) {
    uint32_t a;
    asm("{ .reg .u64 t; cvta.to.shared.u64 t, %1; cvt.u32.u64 %0, t; }" : "=r"(a) : "l"(p));
    return a;
}
#define CP16(d, s) asm volatile("cp.async.cg.shared.global [%0], [%1], 16;" :: "r"(d), "l"(s))
#define CPCOMMIT() asm volatile("cp.async.commit_group;" ::: "memory")
#define CPWAIT1()  asm volatile("cp.async.wait_group 1;" ::: "memory")
#define CPWAIT0()  asm volatile("cp.async.wait_group 0;" ::: "memory")

// Permuted layout: within each 8-float block of row r, element j (0..3) at
// slot 2*((j + (r>>2))&3), element j+4 at slot+1.
__device__ __forceinline__ int pslot(int d, int rot) {
    return (d & ~7) + 2 * (((d & 3) + rot) & 3) + ((d >> 2) & 1);
}

// ===========================================================================
// Pre-pass: round + permute x, qkv_w, proj_w into device globals.
// One thread per 8-float block. rows: x 8192 | qkv_w 1536 | proj_w 512.
// ===========================================================================
__global__ __launch_bounds__(256) void preperm(const float* __restrict__ x,
                                               const float* __restrict__ wq,
                                               const float* __restrict__ wp) {
    int idx = blockIdx.x * 256 + threadIdx.x;
    if (idx >= 10240 * 64) return;
    int row = idx >> 6, blk = idx & 63;
    const float* src; float* dst; int r;
    if (row < 8192)      { r = row;        src = x  + (size_t)r * 512; dst = g_xp    + (size_t)r * 512; }
    else if (row < 9728) { r = row - 8192; src = wq + (size_t)r * 512; dst = g_wqkvp + (size_t)r * 512; }
    else                 { r = row - 9728; src = wp + (size_t)r * 512; dst = g_wprojp + (size_t)r * 512; }
    const float4* s4 = (const float4*)(src + blk * 8);
    float4 lo = s4[0], hi = s4[1];
    int rot = (r >> 2) & 3;
    float t[8];
    t[2 * ((0 + rot) & 3)] = rndf(lo.x); t[2 * ((0 + rot) & 3) + 1] = rndf(hi.x);
    t[2 * ((1 + rot) & 3)] = rndf(lo.y); t[2 * ((1 + rot) & 3) + 1] = rndf(hi.y);
    t[2 * ((2 + rot) & 3)] = rndf(lo.z); t[2 * ((2 + rot) & 3) + 1] = rndf(hi.z);
    t[2 * ((3 + rot) & 3)] = rndf(lo.w); t[2 * ((3 + rot) & 3) + 1] = rndf(hi.w);
    float4* d4 = (float4*)(dst + blk * 8);
    d4[0] = make_float4(t[0], t[1], t[2], t[3]);
    d4[1] = make_float4(t[4], t[5], t[6], t[7]);
}

// ===========================================================================
// GEMM: C[128,128] tile, A/W pre-rounded+permuted in gmem, cp.async staging.
// 128 thr, 4 warps (2x2), warp tile 64x64, BK=32 double-buffered.
// mode 0: A=g_xp, B=g_wqkvp, scatter q/k (permuted) + v (natural)
// mode 1: A=g_attnp, B=g_wprojp, +bias -> Out
// ===========================================================================
#define GP 40
#define GSTAGE (2 * 128 * GP)               // floats per stage
#define GEMM_SMEM (2 * GSTAGE * 4)          // 81920 B

__global__ __launch_bounds__(128, 2) void mma_gemm(const float* __restrict__ Bvec,
                                                   float* __restrict__ Out,
                                                   int mode) {
    extern __shared__ float sm[];
    const uint32_t sbase = smem_u32(sm);
    const int tid = threadIdx.x, wid = tid >> 5, lane = tid & 31;
    const int g = lane >> 2, th = lane & 3;
    const int wm = wid >> 1, wn = wid & 1;
    const int bm = blockIdx.x * 128, bn = blockIdx.y * 128;

    const float* Ap = mode ? g_attnp : g_xp;
    const float* Wp = mode ? g_wprojp : g_wqkvp;
    const float* ga = Ap + (size_t)(bm + tid) * 512;
    const float* gb = Wp + (size_t)(bn + tid) * 512;
    const uint32_t dA = sbase + tid * GP * 4;
    const uint32_t dB = dA + 128 * GP * 4;

    int offA0[4], offA1[4], offB[8];
#pragma unroll
    for (int ma = 0; ma < 4; ma++) {
        int ra = wm * 64 + ma * 16 + g;
        offA0[ma] = ra * GP + 2 * ((th + (ra >> 2)) & 3);
        int rb = ra + 8;
        offA1[ma] = rb * GP + 2 * ((th + (rb >> 2)) & 3);
    }
#pragma unroll
    for (int nb = 0; nb < 8; nb++) {
        int rc = wn * 64 + nb * 8 + g;
        offB[nb] = rc * GP + 2 * ((th + (rc >> 2)) & 3);
    }

    float acc[4][8][4];
#pragma unroll
    for (int i = 0; i < 4; i++)
#pragma unroll
        for (int j = 0; j < 8; j++)
#pragma unroll
            for (int q = 0; q < 4; q++) acc[i][j][q] = 0.0f;

#define G_ISSUE(I)                                                        \
    {                                                                     \
        int _st = (I) & 1;                                                \
        uint32_t _a = dA + _st * GSTAGE * 4;                              \
        uint32_t _b = dB + _st * GSTAGE * 4;                              \
        const float* _sa = ga + (I) * 32;                                 \
        const float* _sb = gb + (I) * 32;                                 \
        _Pragma("unroll")                                                 \
        for (int c = 0; c < 8; c++) {                                     \
            CP16(_a + c * 16, _sa + c * 4);                               \
            CP16(_b + c * 16, _sb + c * 4);                               \
        }                                                                 \
        CPCOMMIT();                                                       \
    }

    G_ISSUE(0);
    G_ISSUE(1);

    for (int i = 0; i < 16; i++) {
        if (i < 15) CPWAIT1(); else CPWAIT0();
        __syncthreads();
        const float* A = sm + (i & 1) * GSTAGE;
        const float* B = A + 128 * GP;
#pragma unroll
        for (int s = 0; s < 4; s++) {
            uint32_t Af[4][4];
#pragma unroll
            for (int ma = 0; ma < 4; ma++) {
                float2 lo = *(const float2*)(A + offA0[ma] + 8 * s);
                float2 hi = *(const float2*)(A + offA1[ma] + 8 * s);
                Af[ma][0] = __float_as_uint(lo.x); Af[ma][1] = __float_as_uint(hi.x);
                Af[ma][2] = __float_as_uint(lo.y); Af[ma][3] = __float_as_uint(hi.y);
            }
#pragma unroll
            for (int nb = 0; nb < 8; nb++) {
                float2 bv = *(const float2*)(B + offB[nb] + 8 * s);
                uint32_t b0 = __float_as_uint(bv.x), b1 = __float_as_uint(bv.y);
#pragma unroll
                for (int ma = 0; ma < 4; ma++) mma8(acc[ma][nb], Af[ma], b0, b1);
            }
        }
        __syncthreads();
        if (i + 2 < 16) G_ISSUE(i + 2);
    }

#pragma unroll
    for (int ma = 0; ma < 4; ma++) {
#pragma unroll
        for (int nb = 0; nb < 8; nb++) {
            int r0 = bm + wm * 64 + ma * 16 + g;
            int cg = bn + wn * 64 + nb * 8 + 2 * th;
#pragma unroll
            for (int e = 0; e < 2; e++) {
                int rr = r0 + e * 8;
                float v0 = acc[ma][nb][2 * e], v1 = acc[ma][nb][2 * e + 1];
                if (mode == 0) {
                    int bb = rr >> 10, n = rr & 1023;
                    int which = cg >> 9, hh = (cg >> 6) & 7, dd = cg & 63;
                    size_t off = (((size_t)(bb * NH + hh)) * NSEQ + n) * HD;
                    int rot = (n >> 2) & 3;
                    if (which == 0) {
                        g_q[off + pslot(dd, rot)]     = rndf(v0 * QK_SCALE);
                        g_q[off + pslot(dd + 1, rot)] = rndf(v1 * QK_SCALE);
                    } else if (which == 1) {
                        g_k[off + pslot(dd, rot)]     = rndf(v0);
                        g_k[off + pslot(dd + 1, rot)] = rndf(v1);
                    } else {
                        float2 o; o.x = rndf(v0); o.y = rndf(v1);
                        *(float2*)(g_v + off + dd) = o;
                    }
                } else {
                    float2 bv = *(const float2*)(Bvec + cg);
                    float2 o; o.x = v0 + bv.x; o.y = v1 + bv.y;
                    *(float2*)(Out + (size_t)rr * 512 + cg) = o;
                }
            }
        }
    }
}

// ===========================================================================
// Flash attention. Grid (8 qt, 8 h, 8 b), 256 thr, 8 warps (16 q-rows each).
// K (permuted) and V (natural) tiles via double-buffered cp.async.
// K B-frags: LDS.64 pairs; V B-frags: 2x LDS.32 (conflict-free, no transpose).
// ===========================================================================
#define AKP 72
#define ASTAGE (2 * 64 * AKP)               // K + V floats per stage
#define ATT_SMEM (2 * ASTAGE * 4)           // 73728 B

__global__ __launch_bounds__(256) void attn_mma(const float* __restrict__ bias) {
    extern __shared__ float sm[];
    const uint32_t sbase = smem_u32(sm);
    const int qt = blockIdx.x, h = blockIdx.y, b = blockIdx.z;
    const int tid = threadIdx.x, wid = tid >> 5, lane = tid & 31;
    const int g = lane >> 2, th = lane & 3;

    const size_t bh = (size_t)(b * NH + h);
    const float* Kg = g_k + bh * NSEQ * HD;
    const float* Vg = g_v + bh * NSEQ * HD;

    // Q fragments via LDG.64 from permuted g_q
    const int qrow = qt * 128 + wid * 16 + g;
    const float* Q0 = g_q + (bh * NSEQ + qrow) * HD;
    const float* Q1 = Q0 + 8 * HD;
    const int rq0 = 2 * ((th + (qrow >> 2)) & 3);
    const int rq1 = 2 * ((th + ((qrow + 8) >> 2)) & 3);
    uint32_t qa[8][4];
#pragma unroll
    for (int s = 0; s < 8; s++) {
        float2 a0 = *(const float2*)(Q0 + 8 * s + rq0);
        float2 a1 = *(const float2*)(Q1 + 8 * s + rq1);
        qa[s][0] = __float_as_uint(a0.x); qa[s][2] = __float_as_uint(a0.y);
        qa[s][1] = __float_as_uint(a1.x); qa[s][3] = __float_as_uint(a1.y);
    }

    // K fragment offsets (rotation folded)
    int offK[8];
#pragma unroll
    for (int na = 0; na < 8; na++) {
        int rc = na * 8 + g;
        offK[na] = rc * AKP + 2 * ((th + (rc >> 2)) & 3);
    }

    float O[8][4];
#pragma unroll
    for (int na = 0; na < 8; na++)
#pragma unroll
        for (int q = 0; q < 4; q++) O[na][q] = 0.0f;
    float mrow[2] = {-INFINITY, -INFINITY};
    float lrow[2] = {0.0f, 0.0f};

    // cp.async assignment: row = tid>>2 (0..63), quarter = tid&3
    const int arow = tid >> 2, aq = tid & 3;

#define A_ISSUE(T)                                                            \
    {                                                                         \
        int _st = (T) & 1;                                                    \
        uint32_t _kd = sbase + (_st * ASTAGE + arow * AKP + aq * 16) * 4;     \
        uint32_t _vd = _kd + 64 * AKP * 4;                                    \
        const float* _ks = Kg + ((size_t)((T) * 64 + arow)) * 64 + aq * 16;   \
        const float* _vs = Vg + ((size_t)((T) * 64 + arow)) * 64 + aq * 16;   \
        _Pragma("unroll")                                                     \
        for (int c = 0; c < 4; c++) {                                         \
            CP16(_kd + c * 16, _ks + c * 4);                                  \
            CP16(_vd + c * 16, _vs + c * 4);                                  \
        }                                                                     \
        CPCOMMIT();                                                           \
    }

    A_ISSUE(0);

    for (int t = 0; t < 16; t++) {
        if (t < 15) { A_ISSUE(t + 1); CPWAIT1(); } else { CPWAIT0(); }
        __syncthreads();
        const float* Ks = sm + (t & 1) * ASTAGE;
        const float* Vs = Ks + 64 * AKP;

        // S = Q K^T
        float S[8][4];
#pragma unroll
        for (int na = 0; na < 8; na++)
#pragma unroll
            for (int q = 0; q < 4; q++) S[na][q] = 0.0f;
#pragma unroll
        for (int s = 0; s < 8; s++) {
#pragma unroll
            for (int na = 0; na < 8; na++) {
                float2 bv = *(const float2*)(Ks + offK[na] + 8 * s);
                mma8(S[na], qa[s], __float_as_uint(bv.x), __float_as_uint(bv.y));
            }
        }

        const float* bp0 = bias + ((size_t)h * NSEQ + qrow) * NSEQ + t * 64 + 2 * th;
        const float* bp1 = bp0 + 8 * NSEQ;
#pragma unroll
        for (int na = 0; na < 8; na++) {
            float2 b0v = *(const float2*)(bp0 + na * 8);
            float2 b1v = *(const float2*)(bp1 + na * 8);
            S[na][0] += b0v.x; S[na][1] += b0v.y;
            S[na][2] += b1v.x; S[na][3] += b1v.y;
        }

#pragma unroll
        for (int e = 0; e < 2; e++) {
            float mx = -INFINITY;
#pragma unroll
            for (int na = 0; na < 8; na++)
                mx = fmaxf(mx, fmaxf(S[na][2 * e], S[na][2 * e + 1]));
            mx = fmaxf(mx, __shfl_xor_sync(0xffffffffu, mx, 1));
            mx = fmaxf(mx, __shfl_xor_sync(0xffffffffu, mx, 2));
            float mn = fmaxf(mrow[e], mx);
            float al = __expf(mrow[e] - mn);
            mrow[e] = mn;
            float ls = 0.0f;
#pragma unroll
            for (int na = 0; na < 8; na++) {
                S[na][2 * e]     = __expf(S[na][2 * e] - mn);
                S[na][2 * e + 1] = __expf(S[na][2 * e + 1] - mn);
                ls += S[na][2 * e] + S[na][2 * e + 1];
            }
            ls += __shfl_xor_sync(0xffffffffu, ls, 1);
            ls += __shfl_xor_sync(0xffffffffu, ls, 2);
            lrow[e] = lrow[e] * al + ls;
#pragma unroll
            for (int na = 0; na < 8; na++) { O[na][2 * e] *= al; O[na][2 * e + 1] *= al; }
        }

#pragma unroll
        for (int na = 0; na < 8; na++)
#pragma unroll
            for (int q = 0; q < 4; q++) S[na][q] = __uint_as_float(f2tf(S[na][q]));

        // O += P V : re-fragment P via quad shuffles, V frags as 2x LDS.32
        const int src0 = (lane & ~3) | (th >> 1);
        const int src2 = src0 + 2;
        const bool odd = (th & 1);
#pragma unroll
        for (int s = 0; s < 8; s++) {
            float x0 = __shfl_sync(0xffffffffu, S[s][0], src0);
            float x1 = __shfl_sync(0xffffffffu, S[s][1], src0);
            float y0 = __shfl_sync(0xffffffffu, S[s][2], src0);
            float y1 = __shfl_sync(0xffffffffu, S[s][3], src0);
            float z0 = __shfl_sync(0xffffffffu, S[s][0], src2);
            float z1 = __shfl_sync(0xffffffffu, S[s][1], src2);
            float w0 = __shfl_sync(0xffffffffu, S[s][2], src2);
            float w1 = __shfl_sync(0xffffffffu, S[s][3], src2);
            uint32_t a[4];
            a[0] = __float_as_uint(odd ? x1 : x0);
            a[1] = __float_as_uint(odd ? y1 : y0);
            a[2] = __float_as_uint(odd ? z1 : z0);
            a[3] = __float_as_uint(odd ? w1 : w0);
            const float* vr0 = Vs + (8 * s + th) * AKP + g;
            const float* vr1 = Vs + (8 * s + th + 4) * AKP + g;
#pragma unroll
            for (int na = 0; na < 8; na++) {
                uint32_t b0 = __float_as_uint(vr0[na * 8]);
                uint32_t b1 = __float_as_uint(vr1[na * 8]);
                mma8(O[na], a, b0, b1);
            }
        }
        __syncthreads();
    }

    // normalize + write g_attnp (permuted, rounded) for the proj GEMM
    const float i0 = 1.0f / lrow[0];
    const float i1 = 1.0f / lrow[1];
    const int rot0 = (qrow >> 2) & 3;
    const int rot1 = ((qrow + 8) >> 2) & 3;
    float* ob0 = g_attnp + ((size_t)b * NSEQ + qrow) * DIMC;
    float* ob1 = ob0 + (size_t)8 * DIMC;
#pragma unroll
    for (int na = 0; na < 8; na++) {
        int c = h * 64 + na * 8 + 2 * th;
        ob0[pslot(c, rot0)]     = rndf(O[na][0] * i0);
        ob0[pslot(c + 1, rot0)] = rndf(O[na][1] * i0);
        ob1[pslot(c, rot1)]     = rndf(O[na][2] * i1);
        ob1[pslot(c + 1, rot1)] = rndf(O[na][3] * i1);
    }
}

extern "C" void kernel_launch(void* const* d_in, const int* in_sizes, int n_in,
                              void* d_out, int out_size) {
    const float* x      = (const float*)d_in[0];
    const float* rpe    = (const float*)d_in[1];
    const float* qkv_w  = (const float*)d_in[2];
    const float* proj_w = (const float*)d_in[3];
    const float* proj_b = (const float*)d_in[4];
    float* out = (float*)d_out;

    preperm<<<(10240 * 64 + 255) / 256, 256>>>(x, qkv_w, proj_w);
    cudaFuncSetAttribute(mma_gemm, cudaFuncAttributeMaxDynamicSharedMemorySize, GEMM_SMEM);
    cudaFuncSetAttribute(attn_mma, cudaFuncAttributeMaxDynamicSharedMemorySize, ATT_SMEM);
    mma_gemm<<<dim3(64, 12), 128, GEMM_SMEM>>>(nullptr, nullptr, 0);
    attn_mma<<<dim3(8, 8, 8), 256, ATT_SMEM>>>(rpe);
    mma_gemm<<<dim3(64, 4), 128, GEMM_SMEM>>>(proj_b, out, 1);
}

// round 9
// speedup vs baseline: 1.0001x; 1.0001x over previous
#include <cuda_runtime.h>
#include <cstdint>
#include <math.h>

#define DIMC  512
#define NH    8
#define HD    64
#define NB    8
#define NSEQ  1024
#define QK_SCALE 0.125f

// Scratch (device globals)
__device__ float g_q[NB * NH * NSEQ * HD];      // permuted, rounded, scaled
__device__ float g_k[NB * NH * NSEQ * HD];      // permuted, rounded
__device__ float g_v[NB * NH * NSEQ * HD];      // natural, rounded
__device__ float g_attnp[NB * NSEQ * DIMC];     // permuted, rounded
__device__ float g_xp[NB * NSEQ * DIMC];        // permuted, rounded x
__device__ float g_wqkvp[3 * DIMC * DIMC];      // permuted, rounded qkv_w
__device__ float g_wprojp[DIMC * DIMC];         // permuted, rounded proj_w

__device__ __forceinline__ uint32_t f2tf(float f) {
    uint32_t r;
    asm("cvt.rna.tf32.f32 %0, %1;" : "=r"(r) : "f"(f));
    return r;
}
__device__ __forceinline__ float rndf(float f) { return __uint_as_float(f2tf(f)); }
__device__ __forceinline__ void mma8(float* d, const uint32_t* a, uint32_t b0, uint32_t b1) {
    asm volatile(
        "mma.sync.aligned.m16n8k8.row.col.f32.tf32.tf32.f32 "
        "{%0,%1,%2,%3}, {%4,%5,%6,%7}, {%8,%9}, {%0,%1,%2,%3};"
        : "+f"(d[0]), "+f"(d[1]), "+f"(d[2]), "+f"(d[3])
        : "r"(a[0]), "r"(a[1]), "r"(a[2]), "r"(a[3]), "r"(b0), "r"(b1));
}
__device__ __forceinline__ uint32_t smem_u32(const void* p) {
    uint32_t a;
    asm("{ .reg .u64 t; cvta.to.shared.u64 t, %1; cvt.u32.u64 %0, t; }" : "=r"(a) : "l"(p));
    return a;
}
#define CP16(d, s) asm volatile("cp.async.cg.shared.global [%0], [%1], 16;" :: "r"(d), "l"(s))
#define CPCOMMIT() asm volatile("cp.async.commit_group;" ::: "memory")
#define CPWAIT1()  asm volatile("cp.async.wait_group 1;" ::: "memory")
#define CPWAIT0()  asm volatile("cp.async.wait_group 0;" ::: "memory")

__device__ __forceinline__ int pslot(int d, int rot) {
    return (d & ~7) + 2 * (((d & 3) + rot) & 3) + ((d >> 2) & 1);
}

// ===========================================================================
// Pre-pass: round + permute x, qkv_w, proj_w.
// ===========================================================================
__global__ __launch_bounds__(256) void preperm(const float* __restrict__ x,
                                               const float* __restrict__ wq,
                                               const float* __restrict__ wp) {
    int idx = blockIdx.x * 256 + threadIdx.x;
    if (idx >= 10240 * 64) return;
    int row = idx >> 6, blk = idx & 63;
    const float* src; float* dst; int r;
    if (row < 8192)      { r = row;        src = x  + (size_t)r * 512; dst = g_xp    + (size_t)r * 512; }
    else if (row < 9728) { r = row - 8192; src = wq + (size_t)r * 512; dst = g_wqkvp + (size_t)r * 512; }
    else                 { r = row - 9728; src = wp + (size_t)r * 512; dst = g_wprojp + (size_t)r * 512; }
    const float4* s4 = (const float4*)(src + blk * 8);
    float4 lo = s4[0], hi = s4[1];
    int rot = (r >> 2) & 3;
    float t[8];
    t[2 * ((0 + rot) & 3)] = rndf(lo.x); t[2 * ((0 + rot) & 3) + 1] = rndf(hi.x);
    t[2 * ((1 + rot) & 3)] = rndf(lo.y); t[2 * ((1 + rot) & 3) + 1] = rndf(hi.y);
    t[2 * ((2 + rot) & 3)] = rndf(lo.z); t[2 * ((2 + rot) & 3) + 1] = rndf(hi.z);
    t[2 * ((3 + rot) & 3)] = rndf(lo.w); t[2 * ((3 + rot) & 3) + 1] = rndf(hi.w);
    float4* d4 = (float4*)(dst + blk * 8);
    d4[0] = make_float4(t[0], t[1], t[2], t[3]);
    d4[1] = make_float4(t[4], t[5], t[6], t[7]);
}

// ===========================================================================
// GEMM: CTA 128x128, 256 thr, 8 warps (2x4), warp tile 64x32, BK=32,
// cp.async double-buffered, inputs pre-rounded+permuted in gmem.
// ===========================================================================
#define GP 40
#define GSTAGE (2 * 128 * GP)
#define GEMM_SMEM (2 * GSTAGE * 4)          // 81920 B

__global__ __launch_bounds__(256, 2) void mma_gemm(const float* __restrict__ Bvec,
                                                   float* __restrict__ Out,
                                                   int mode) {
    extern __shared__ float sm[];
    const uint32_t sbase = smem_u32(sm);
    const int tid = threadIdx.x, wid = tid >> 5, lane = tid & 31;
    const int g = lane >> 2, th = lane & 3;
    const int wm = wid >> 2, wn = wid & 3;
    const int bm = blockIdx.x * 128, bn = blockIdx.y * 128;

    const float* Ap = mode ? g_attnp : g_xp;
    const float* Wp = mode ? g_wprojp : g_wqkvp;

    // loader: threads 0..127 -> A row tid; 128..255 -> B row tid-128
    const int lrow = tid & 127, side = tid >> 7;
    const float* gsrc = side ? (Wp + (size_t)(bn + lrow) * 512)
                             : (Ap + (size_t)(bm + lrow) * 512);
    const uint32_t dst0 = sbase + (uint32_t)(side * 128 * GP + lrow * GP) * 4;

    int offA0[4], offA1[4], offB[4];
#pragma unroll
    for (int ma = 0; ma < 4; ma++) {
        int ra = wm * 64 + ma * 16 + g;
        offA0[ma] = ra * GP + 2 * ((th + (ra >> 2)) & 3);
        int rb = ra + 8;
        offA1[ma] = rb * GP + 2 * ((th + (rb >> 2)) & 3);
    }
#pragma unroll
    for (int nb = 0; nb < 4; nb++) {
        int rc = wn * 32 + nb * 8 + g;
        offB[nb] = rc * GP + 2 * ((th + (rc >> 2)) & 3);
    }

    float acc[4][4][4];
#pragma unroll
    for (int i = 0; i < 4; i++)
#pragma unroll
        for (int j = 0; j < 4; j++)
#pragma unroll
            for (int q = 0; q < 4; q++) acc[i][j][q] = 0.0f;

#define G_ISSUE(I)                                                        \
    {                                                                     \
        uint32_t _d = dst0 + ((I) & 1) * GSTAGE * 4;                      \
        const float* _s = gsrc + (I) * 32;                                \
        _Pragma("unroll")                                                 \
        for (int c = 0; c < 8; c++) CP16(_d + c * 16, _s + c * 4);        \
        CPCOMMIT();                                                       \
    }

    G_ISSUE(0);
    G_ISSUE(1);

    for (int i = 0; i < 16; i++) {
        if (i < 15) CPWAIT1(); else CPWAIT0();
        __syncthreads();
        const float* A = sm + (i & 1) * GSTAGE;
        const float* B = A + 128 * GP;
#pragma unroll
        for (int s = 0; s < 4; s++) {
            uint32_t Af[4][4];
#pragma unroll
            for (int ma = 0; ma < 4; ma++) {
                float2 lo = *(const float2*)(A + offA0[ma] + 8 * s);
                float2 hi = *(const float2*)(A + offA1[ma] + 8 * s);
                Af[ma][0] = __float_as_uint(lo.x); Af[ma][1] = __float_as_uint(hi.x);
                Af[ma][2] = __float_as_uint(lo.y); Af[ma][3] = __float_as_uint(hi.y);
            }
#pragma unroll
            for (int nb = 0; nb < 4; nb++) {
                float2 bv = *(const float2*)(B + offB[nb] + 8 * s);
                uint32_t b0 = __float_as_uint(bv.x), b1 = __float_as_uint(bv.y);
#pragma unroll
                for (int ma = 0; ma < 4; ma++) mma8(acc[ma][nb], Af[ma], b0, b1);
            }
        }
        __syncthreads();
        if (i + 2 < 16) G_ISSUE(i + 2);
    }

#pragma unroll
    for (int ma = 0; ma < 4; ma++) {
#pragma unroll
        for (int nb = 0; nb < 4; nb++) {
            int r0 = bm + wm * 64 + ma * 16 + g;
            int cg = bn + wn * 32 + nb * 8 + 2 * th;
#pragma unroll
            for (int e = 0; e < 2; e++) {
                int rr = r0 + e * 8;
                float v0 = acc[ma][nb][2 * e], v1 = acc[ma][nb][2 * e + 1];
                if (mode == 0) {
                    int bb = rr >> 10, n = rr & 1023;
                    int which = cg >> 9, hh = (cg >> 6) & 7, dd = cg & 63;
                    size_t off = (((size_t)(bb * NH + hh)) * NSEQ + n) * HD;
                    int rot = (n >> 2) & 3;
                    if (which == 0) {
                        g_q[off + pslot(dd, rot)]     = rndf(v0 * QK_SCALE);
                        g_q[off + pslot(dd + 1, rot)] = rndf(v1 * QK_SCALE);
                    } else if (which == 1) {
                        g_k[off + pslot(dd, rot)]     = rndf(v0);
                        g_k[off + pslot(dd + 1, rot)] = rndf(v1);
                    } else {
                        float2 o; o.x = rndf(v0); o.y = rndf(v1);
                        *(float2*)(g_v + off + dd) = o;
                    }
                } else {
                    float2 bv = *(const float2*)(Bvec + cg);
                    float2 o; o.x = v0 + bv.x; o.y = v1 + bv.y;
                    *(float2*)(Out + (size_t)rr * 512 + cg) = o;
                }
            }
        }
    }
}

// ===========================================================================
// Flash attention (unchanged from R7). Grid (8,8,8), 256 thr, 8 warps.
// ===========================================================================
#define AKP 72
#define ASTAGE (2 * 64 * AKP)
#define ATT_SMEM (2 * ASTAGE * 4)           // 73728 B

__global__ __launch_bounds__(256) void attn_mma(const float* __restrict__ bias) {
    extern __shared__ float sm[];
    const uint32_t sbase = smem_u32(sm);
    const int qt = blockIdx.x, h = blockIdx.y, b = blockIdx.z;
    const int tid = threadIdx.x, wid = tid >> 5, lane = tid & 31;
    const int g = lane >> 2, th = lane & 3;

    const size_t bh = (size_t)(b * NH + h);
    const float* Kg = g_k + bh * NSEQ * HD;
    const float* Vg = g_v + bh * NSEQ * HD;

    const int qrow = qt * 128 + wid * 16 + g;
    const float* Q0 = g_q + (bh * NSEQ + qrow) * HD;
    const float* Q1 = Q0 + 8 * HD;
    const int rq0 = 2 * ((th + (qrow >> 2)) & 3);
    const int rq1 = 2 * ((th + ((qrow + 8) >> 2)) & 3);
    uint32_t qa[8][4];
#pragma unroll
    for (int s = 0; s < 8; s++) {
        float2 a0 = *(const float2*)(Q0 + 8 * s + rq0);
        float2 a1 = *(const float2*)(Q1 + 8 * s + rq1);
        qa[s][0] = __float_as_uint(a0.x); qa[s][2] = __float_as_uint(a0.y);
        qa[s][1] = __float_as_uint(a1.x); qa[s][3] = __float_as_uint(a1.y);
    }

    int offK[8];
#pragma unroll
    for (int na = 0; na < 8; na++) {
        int rc = na * 8 + g;
        offK[na] = rc * AKP + 2 * ((th + (rc >> 2)) & 3);
    }

    float O[8][4];
#pragma unroll
    for (int na = 0; na < 8; na++)
#pragma unroll
        for (int q = 0; q < 4; q++) O[na][q] = 0.0f;
    float mrow[2] = {-INFINITY, -INFINITY};
    float lrow[2] = {0.0f, 0.0f};

    const int arow = tid >> 2, aq = tid & 3;

#define A_ISSUE(T)                                                            \
    {                                                                         \
        int _st = (T) & 1;                                                    \
        uint32_t _kd = sbase + (_st * ASTAGE + arow * AKP + aq * 16) * 4;     \
        uint32_t _vd = _kd + 64 * AKP * 4;                                    \
        const float* _ks = Kg + ((size_t)((T) * 64 + arow)) * 64 + aq * 16;   \
        const float* _vs = Vg + ((size_t)((T) * 64 + arow)) * 64 + aq * 16;   \
        _Pragma("unroll")                                                     \
        for (int c = 0; c < 4; c++) {                                         \
            CP16(_kd + c * 16, _ks + c * 4);                                  \
            CP16(_vd + c * 16, _vs + c * 4);                                  \
        }                                                                     \
        CPCOMMIT();                                                           \
    }

    A_ISSUE(0);

    for (int t = 0; t < 16; t++) {
        if (t < 15) { A_ISSUE(t + 1); CPWAIT1(); } else { CPWAIT0(); }
        __syncthreads();
        const float* Ks = sm + (t & 1) * ASTAGE;
        const float* Vs = Ks + 64 * AKP;

        float S[8][4];
#pragma unroll
        for (int na = 0; na < 8; na++)
#pragma unroll
            for (int q = 0; q < 4; q++) S[na][q] = 0.0f;
#pragma unroll
        for (int s = 0; s < 8; s++) {
#pragma unroll
            for (int na = 0; na < 8; na++) {
                float2 bv = *(const float2*)(Ks + offK[na] + 8 * s);
                mma8(S[na], qa[s], __float_as_uint(bv.x), __float_as_uint(bv.y));
            }
        }

        const float* bp0 = bias + ((size_t)h * NSEQ + qrow) * NSEQ + t * 64 + 2 * th;
        const float* bp1 = bp0 + 8 * NSEQ;
#pragma unroll
        for (int na = 0; na < 8; na++) {
            float2 b0v = *(const float2*)(bp0 + na * 8);
            float2 b1v = *(const float2*)(bp1 + na * 8);
            S[na][0] += b0v.x; S[na][1] += b0v.y;
            S[na][2] += b1v.x; S[na][3] += b1v.y;
        }

#pragma unroll
        for (int e = 0; e < 2; e++) {
            float mx = -INFINITY;
#pragma unroll
            for (int na = 0; na < 8; na++)
                mx = fmaxf(mx, fmaxf(S[na][2 * e], S[na][2 * e + 1]));
            mx = fmaxf(mx, __shfl_xor_sync(0xffffffffu, mx, 1));
            mx = fmaxf(mx, __shfl_xor_sync(0xffffffffu, mx, 2));
            float mn = fmaxf(mrow[e], mx);
            float al = __expf(mrow[e] - mn);
            mrow[e] = mn;
            float ls = 0.0f;
#pragma unroll
            for (int na = 0; na < 8; na++) {
                S[na][2 * e]     = __expf(S[na][2 * e] - mn);
                S[na][2 * e + 1] = __expf(S[na][2 * e + 1] - mn);
                ls += S[na][2 * e] + S[na][2 * e + 1];
            }
            ls += __shfl_xor_sync(0xffffffffu, ls, 1);
            ls += __shfl_xor_sync(0xffffffffu, ls, 2);
            lrow[e] = lrow[e] * al + ls;
#pragma unroll
            for (int na = 0; na < 8; na++) { O[na][2 * e] *= al; O[na][2 * e + 1] *= al; }
        }

#pragma unroll
        for (int na = 0; na < 8; na++)
#pragma unroll
            for (int q = 0; q < 4; q++) S[na][q] = __uint_as_float(f2tf(S[na][q]));

        const int src0 = (lane & ~3) | (th >> 1);
        const int src2 = src0 + 2;
        const bool odd = (th & 1);
#pragma unroll
        for (int s = 0; s < 8; s++) {
            float x0 = __shfl_sync(0xffffffffu, S[s][0], src0);
            float x1 = __shfl_sync(0xffffffffu, S[s][1], src0);
            float y0 = __shfl_sync(0xffffffffu, S[s][2], src0);
            float y1 = __shfl_sync(0xffffffffu, S[s][3], src0);
            float z0 = __shfl_sync(0xffffffffu, S[s][0], src2);
            float z1 = __shfl_sync(0xffffffffu, S[s][1], src2);
            float w0 = __shfl_sync(0xffffffffu, S[s][2], src2);
            float w1 = __shfl_sync(0xffffffffu, S[s][3], src2);
            uint32_t a[4];
            a[0] = __float_as_uint(odd ? x1 : x0);
            a[1] = __float_as_uint(odd ? y1 : y0);
            a[2] = __float_as_uint(odd ? z1 : z0);
            a[3] = __float_as_uint(odd ? w1 : w0);
            const float* vr0 = Vs + (8 * s + th) * AKP + g;
            const float* vr1 = Vs + (8 * s + th + 4) * AKP + g;
#pragma unroll
            for (int na = 0; na < 8; na++) {
                uint32_t b0 = __float_as_uint(vr0[na * 8]);
                uint32_t b1 = __float_as_uint(vr1[na * 8]);
                mma8(O[na], a, b0, b1);
            }
        }
        __syncthreads();
    }

    const float i0 = 1.0f / lrow[0];
    const float i1 = 1.0f / lrow[1];
    const int rot0 = (qrow >> 2) & 3;
    const int rot1 = ((qrow + 8) >> 2) & 3;
    float* ob0 = g_attnp + ((size_t)b * NSEQ + qrow) * DIMC;
    float* ob1 = ob0 + (size_t)8 * DIMC;
#pragma unroll
    for (int na = 0; na < 8; na++) {
        int c = h * 64 + na * 8 + 2 * th;
        ob0[pslot(c, rot0)]     = rndf(O[na][0] * i0);
        ob0[pslot(c + 1, rot0)] = rndf(O[na][1] * i0);
        ob1[pslot(c, rot1)]     = rndf(O[na][2] * i1);
        ob1[pslot(c + 1, rot1)] = rndf(O[na][3] * i1);
    }
}

extern "C" void kernel_launch(void* const* d_in, const int* in_sizes, int n_in,
                              void* d_out, int out_size) {
    const float* x      = (const float*)d_in[0];
    const float* rpe    = (const float*)d_in[1];
    const float* qkv_w  = (const float*)d_in[2];
    const float* proj_w = (const float*)d_in[3];
    const float* proj_b = (const float*)d_in[4];
    float* out = (float*)d_out;

    preperm<<<(10240 * 64 + 255) / 256, 256>>>(x, qkv_w, proj_w);
    cudaFuncSetAttribute(mma_gemm, cudaFuncAttributeMaxDynamicSharedMemorySize, GEMM_SMEM);
    cudaFuncSetAttribute(attn_mma, cudaFuncAttributeMaxDynamicSharedMemorySize, ATT_SMEM);
    mma_gemm<<<dim3(64, 12), 256, GEMM_SMEM>>>(nullptr, nullptr, 0);
    attn_mma<<<dim3(8, 8, 8), 256, ATT_SMEM>>>(rpe);
    mma_gemm<<<dim3(64, 4), 256, GEMM_SMEM>>>(proj_b, out, 1);
}